// round 1
// baseline (speedup 1.0000x reference)
#include <cuda_runtime.h>
#include <math.h>

#define NH 16
#define HD 64
#define DM 1024
#define LS 2048
#define NB 2
#define LARGE_NEG_F 10000.0f
#define CLAMP_F 20.0f

// ---------------- scratch (no allocations allowed) ----------------
__device__ float g_q[(size_t)NB * NH * LS * HD];      // [B,H,L,d]
__device__ float g_k[(size_t)NB * NH * LS * HD];
__device__ float g_v[(size_t)NB * NH * LS * HD];
__device__ float g_attn[(size_t)NB * LS * DM];        // [B,L,D]
__device__ float g_maskpen[NB * LS];                  // 10000 if padded else 0

// ---------------- mask dtype probe + expand ----------------
// key_padding_mask is a bool array [B,L]; harness dtype is ambiguous.
// Detect via byte pattern: any nonzero byte at offset%4==1 -> uint8;
// else nonzero at offset%4 in {2,3} -> float32 (0x3f800000); else int32.
__global__ void mask_kernel(const unsigned char* __restrict__ m) {
    __shared__ int s_nz1, s_nz23;
    int tid = threadIdx.x;
    if (tid == 0) { s_nz1 = 0; s_nz23 = 0; }
    __syncthreads();
    int nz1 = 0, nz23 = 0;
    for (int i = tid; i < NB * LS; i += blockDim.x) {
        unsigned char v = m[i];
        if (v) {
            int r = i & 3;
            if (r == 1) nz1 = 1;
            else if (r >= 2) nz23 = 1;
        }
    }
    if (nz1) atomicOr(&s_nz1, 1);
    if (nz23) atomicOr(&s_nz23, 1);
    __syncthreads();
    int mode = s_nz1 ? 0 : (s_nz23 ? 2 : 1);  // 0=u8, 1=i32, 2=f32
    for (int i = tid; i < NB * LS; i += blockDim.x) {
        int on;
        if (mode == 0)      on = (m[i] != 0);
        else if (mode == 1) on = (((const int*)m)[i] != 0);
        else                on = (((const float*)m)[i] != 0.0f);
        g_maskpen[i] = on ? LARGE_NEG_F : 0.0f;
    }
}

// ---------------- SGEMM: C[M,N] = A[M,K] @ W[N,K]^T + bias[N] ----------------
// MODE 0: A = x, scatter outputs into g_q/g_k/g_v head-major
// MODE 1: A = g_attn, plain write to C
template <int MODE>
__global__ void __launch_bounds__(256)
gemm_kernel(const float* __restrict__ A_in, const float* __restrict__ W,
            const float* __restrict__ bias, float* __restrict__ C,
            int M, int N, int K) {
    __shared__ float As[8][128];
    __shared__ float Bs[8][128];

    const float* A = (MODE == 0) ? A_in : g_attn;

    int tid = threadIdx.x;
    int bm = blockIdx.y * 128;
    int bn = blockIdx.x * 128;
    int tx = tid & 15;       // 0..15  -> N micro
    int ty = tid >> 4;       // 0..15  -> M micro

    float acc[8][8];
#pragma unroll
    for (int i = 0; i < 8; i++)
#pragma unroll
        for (int j = 0; j < 8; j++) acc[i][j] = 0.0f;

    int lrow = tid >> 1;              // 0..127
    int lcol = (tid & 1) * 4;         // 0 or 4
    const float* Ap = A + (size_t)(bm + lrow) * K + lcol;
    const float* Wp = W + (size_t)(bn + lrow) * K + lcol;

    for (int kt = 0; kt < K; kt += 8) {
        float4 av = *(const float4*)(Ap + kt);
        float4 wv = *(const float4*)(Wp + kt);
        As[lcol + 0][lrow] = av.x; As[lcol + 1][lrow] = av.y;
        As[lcol + 2][lrow] = av.z; As[lcol + 3][lrow] = av.w;
        Bs[lcol + 0][lrow] = wv.x; Bs[lcol + 1][lrow] = wv.y;
        Bs[lcol + 2][lrow] = wv.z; Bs[lcol + 3][lrow] = wv.w;
        __syncthreads();
#pragma unroll
        for (int k = 0; k < 8; k++) {
            float af[8], bf[8];
            *(float4*)(af)     = *(const float4*)&As[k][ty * 8];
            *(float4*)(af + 4) = *(const float4*)&As[k][ty * 8 + 4];
            *(float4*)(bf)     = *(const float4*)&Bs[k][tx * 8];
            *(float4*)(bf + 4) = *(const float4*)&Bs[k][tx * 8 + 4];
#pragma unroll
            for (int i = 0; i < 8; i++)
#pragma unroll
                for (int j = 0; j < 8; j++) acc[i][j] += af[i] * bf[j];
        }
        __syncthreads();
    }

#pragma unroll
    for (int i = 0; i < 8; i++) {
        int m = bm + ty * 8 + i;
#pragma unroll
        for (int j = 0; j < 8; j++) {
            int n = bn + tx * 8 + j;
            float v = acc[i][j] + bias[n];
            if (MODE == 0) {
                int sec = n >> 10;         // 0=q 1=k 2=v (block never straddles)
                int c = n & 1023;
                int h = c >> 6, dd = c & 63;
                int b = m >> 11, l = m & 2047;
                float* dst = (sec == 0) ? g_q : (sec == 1) ? g_k : g_v;
                dst[(((size_t)b * NH + h) * LS + l) * HD + dd] = v;
            } else {
                C[(size_t)m * N + n] = v;
            }
        }
    }
}

// ---------------- flash attention, fp32 ----------------
// grid: (L/64, H, B), block: 256 threads (8 warps)
// Each warp owns 8 q-rows; each lane owns k-columns {lane, lane+32} / d-columns {lane, lane+32}.
__global__ void __launch_bounds__(256)
attn_kernel(const float* __restrict__ bias) {
    __shared__ float Qs[64][64];
    __shared__ float KPs[64][64];   // K^T during S-phase, then P tile
    __shared__ float Vs[64][64];

    int b = blockIdx.z, h = blockIdx.y;
    int q0 = blockIdx.x * 64;
    int tid = threadIdx.x;
    int lane = tid & 31;
    int wid = tid >> 5;
    int qr = wid * 8;

    const float* Qg = g_q + (((size_t)b * NH + h) * LS + q0) * HD;
    const float* Kg = g_k + ((size_t)b * NH + h) * LS * HD;
    const float* Vg = g_v + ((size_t)b * NH + h) * LS * HD;
    const float* biasg = bias + (((size_t)b * NH + h) * LS + q0) * LS;

    // load Q tile [64][64]
    {
        int r = tid >> 4, c4 = (tid & 15) * 4;
#pragma unroll
        for (int j = 0; j < 4; j++) {
            int qq = r + j * 16;
            *(float4*)&Qs[qq][c4] = *(const float4*)(Qg + (size_t)qq * HD + c4);
        }
    }

    float m_i[8], l_i[8], o0[8], o1[8];
#pragma unroll
    for (int i = 0; i < 8; i++) { m_i[i] = -INFINITY; l_i[i] = 0.f; o0[i] = 0.f; o1[i] = 0.f; }

    for (int kt = 0; kt < LS; kt += 64) {
        __syncthreads();   // previous iteration's KPs/Vs consumers done
        {
            int r = tid >> 4, c4 = (tid & 15) * 4;
#pragma unroll
            for (int j = 0; j < 4; j++) {
                int kk = r + j * 16;
                float4 kv = *(const float4*)(Kg + (size_t)(kt + kk) * HD + c4);
                KPs[c4 + 0][kk] = kv.x; KPs[c4 + 1][kk] = kv.y;
                KPs[c4 + 2][kk] = kv.z; KPs[c4 + 3][kk] = kv.w;
                *(float4*)&Vs[kk][c4] = *(const float4*)(Vg + (size_t)(kt + kk) * HD + c4);
            }
        }
        __syncthreads();

        // S = Q @ K^T for this tile
        float s0[8], s1[8];
#pragma unroll
        for (int i = 0; i < 8; i++) { s0[i] = 0.f; s1[i] = 0.f; }
#pragma unroll 4
        for (int dd = 0; dd < 64; dd++) {
            float k0 = KPs[dd][lane];
            float k1 = KPs[dd][lane + 32];
#pragma unroll
            for (int i = 0; i < 8; i++) {
                float qv = Qs[qr + i][dd];
                s0[i] += qv * k0;
                s1[i] += qv * k1;
            }
        }

        // scale + bias + key-padding penalty
        float pen0 = g_maskpen[b * LS + kt + lane];
        float pen1 = g_maskpen[b * LS + kt + lane + 32];
#pragma unroll
        for (int i = 0; i < 8; i++) {
            const float* br = biasg + (size_t)(qr + i) * LS + kt;
            s0[i] = s0[i] * 0.125f + br[lane]      - pen0;
            s1[i] = s1[i] * 0.125f + br[lane + 32] - pen1;
        }

        __syncthreads();   // all warps finished reading KPs as K^T

        // online softmax update; write P tile into KPs (own warp's rows only)
#pragma unroll
        for (int i = 0; i < 8; i++) {
            float v = fmaxf(s0[i], s1[i]);
#pragma unroll
            for (int off = 16; off >= 1; off >>= 1)
                v = fmaxf(v, __shfl_xor_sync(0xffffffffu, v, off));
            float mn = fmaxf(m_i[i], v);
            float sc = __expf(m_i[i] - mn);      // first tile: exp(-inf)=0
            m_i[i] = mn;
            float p0 = __expf(fmaxf(s0[i] - mn, -CLAMP_F));
            float p1 = __expf(fmaxf(s1[i] - mn, -CLAMP_F));
            float r = p0 + p1;
#pragma unroll
            for (int off = 16; off >= 1; off >>= 1)
                r += __shfl_xor_sync(0xffffffffu, r, off);
            l_i[i] = l_i[i] * sc + r;
            o0[i] *= sc; o1[i] *= sc;
            KPs[qr + i][lane] = p0;
            KPs[qr + i][lane + 32] = p1;
        }
        __syncwarp();

        // O += P @ V (each warp reads only its own P rows)
#pragma unroll 4
        for (int k = 0; k < 64; k++) {
            float v0 = Vs[k][lane];
            float v1 = Vs[k][lane + 32];
#pragma unroll
            for (int i = 0; i < 8; i++) {
                float pv = KPs[qr + i][k];
                o0[i] += pv * v0;
                o1[i] += pv * v1;
            }
        }
    }

    // normalize + write to g_attn in [B,L,D] layout (D index = h*64 + d)
#pragma unroll
    for (int i = 0; i < 8; i++) {
        float inv = 1.0f / l_i[i];
        size_t base = ((size_t)b * LS + q0 + qr + i) * DM + h * HD;
        g_attn[base + lane]      = o0[i] * inv;
        g_attn[base + lane + 32] = o1[i] * inv;
    }
}

extern "C" void kernel_launch(void* const* d_in, const int* in_sizes, int n_in,
                              void* d_out, int out_size) {
    const float* x          = (const float*)d_in[0];
    const unsigned char* km = (const unsigned char*)d_in[1];
    const float* attn_bias  = (const float*)d_in[2];
    const float* W_in       = (const float*)d_in[3];
    const float* b_in       = (const float*)d_in[4];
    const float* W_out      = (const float*)d_in[5];
    const float* b_out      = (const float*)d_in[6];
    float* out              = (float*)d_out;
    (void)in_sizes; (void)n_in; (void)out_size;

    mask_kernel<<<1, 256>>>(km);

    // QKV: [4096,1024] @ [3072,1024]^T
    {
        dim3 grid(3072 / 128, 4096 / 128);
        gemm_kernel<0><<<grid, 256>>>(x, W_in, b_in, nullptr, NB * LS, 3 * DM, DM);
    }
    // attention
    {
        dim3 grid(LS / 64, NH, NB);
        attn_kernel<<<grid, 256>>>(attn_bias);
    }
    // out-proj: [4096,1024] @ [1024,1024]^T
    {
        dim3 grid(1024 / 128, 4096 / 128);
        gemm_kernel<1><<<grid, 256>>>(nullptr, W_out, b_out, out, NB * LS, DM, DM);
    }
}

// round 6
// speedup vs baseline: 2.3120x; 2.3120x over previous
#include <cuda_runtime.h>
#include <math.h>

#define NH 16
#define HD 64
#define DM 1024
#define LS 2048
#define NB 2
#define LNEG_F 10000.0f
#define CLAMP_F 20.0f

// ---------------- scratch (no allocations allowed) ----------------
__device__ float g_q[(size_t)NB * NH * LS * HD];      // [B,H,L,d]
__device__ float g_k[(size_t)NB * NH * LS * HD];
__device__ float g_v[(size_t)NB * NH * LS * HD];
__device__ float g_attn[(size_t)NB * LS * DM];        // [B,L,D]
__device__ float g_maskpen[NB * LS];                  // 10000 if padded else 0

// ---------------- helpers ----------------
__device__ __forceinline__ unsigned f2tf(float f) {
    unsigned u;
    asm("cvt.rna.tf32.f32 %0, %1;" : "=r"(u) : "f"(f));
    return u;
}

__device__ __forceinline__ void mma_tf32(float& c0, float& c1, float& c2, float& c3,
                                         unsigned a0, unsigned a1, unsigned a2, unsigned a3,
                                         unsigned b0, unsigned b1) {
    asm volatile(
        "mma.sync.aligned.m16n8k8.row.col.f32.tf32.tf32.f32 "
        "{%0,%1,%2,%3},{%4,%5,%6,%7},{%8,%9},{%0,%1,%2,%3};"
        : "+f"(c0), "+f"(c1), "+f"(c2), "+f"(c3)
        : "r"(a0), "r"(a1), "r"(a2), "r"(a3), "r"(b0), "r"(b1));
}

// ---------------- mask dtype probe + expand ----------------
__global__ void mask_kernel(const unsigned char* __restrict__ m) {
    __shared__ int s_nz1, s_nz23;
    int tid = threadIdx.x;
    if (tid == 0) { s_nz1 = 0; s_nz23 = 0; }
    __syncthreads();
    int nz1 = 0, nz23 = 0;
    for (int i = tid; i < NB * LS; i += blockDim.x) {
        unsigned char v = m[i];
        if (v) {
            int r = i & 3;
            if (r == 1) nz1 = 1;
            else if (r >= 2) nz23 = 1;
        }
    }
    if (nz1) atomicOr(&s_nz1, 1);
    if (nz23) atomicOr(&s_nz23, 1);
    __syncthreads();
    int mode = s_nz1 ? 0 : (s_nz23 ? 2 : 1);  // 0=u8, 1=i32, 2=f32
    for (int i = tid; i < NB * LS; i += blockDim.x) {
        int on;
        if (mode == 0)      on = (m[i] != 0);
        else if (mode == 1) on = (((const int*)m)[i] != 0);
        else                on = (((const float*)m)[i] != 0.0f);
        g_maskpen[i] = on ? LNEG_F : 0.0f;
    }
}

// ---------------- tf32 tensor-core GEMM: C[M,N] = A[M,K] @ W[N,K]^T + bias[N] ----
// block tile 128x128, K-stage 16. 8 warps: warp_m = wid&3 (32 rows), warp_n = wid>>2 (64 cols).
// smem stride 20 floats: (20*g + t) mod 32 hits all banks -> conflict-free frag loads.
// Static smem only (20 KB).
// MODE 0: A = x, scatter q/k/v head-major.  MODE 1: A = g_attn, write C.
template <int MODE>
__global__ void __launch_bounds__(256, 2)
gemm_tc(const float* __restrict__ A_in, const float* __restrict__ W,
        const float* __restrict__ bias, float* __restrict__ C,
        int M, int N, int K) {
    __shared__ unsigned As[128 * 20];
    __shared__ unsigned Bs[128 * 20];

    const float* A = (MODE == 0) ? A_in : g_attn;

    int tid = threadIdx.x, lane = tid & 31, wid = tid >> 5;
    int g = lane >> 2, t = lane & 3;
    int wm = wid & 3, wn = wid >> 2;
    int bm = blockIdx.y * 128, bn = blockIdx.x * 128;

    float acc[2][8][4];
#pragma unroll
    for (int mt = 0; mt < 2; mt++)
#pragma unroll
        for (int nt = 0; nt < 8; nt++)
#pragma unroll
            for (int i = 0; i < 4; i++) acc[mt][nt][i] = 0.0f;

    int lr = tid >> 1;               // 0..127
    int lc = (tid & 1) * 8;          // 0 or 8
    const float* Ap = A + (size_t)(bm + lr) * K + lc;
    const float* Wp = W + (size_t)(bn + lr) * K + lc;

    for (int kt = 0; kt < K; kt += 16) {
        float4 av0 = *(const float4*)(Ap + kt);
        float4 av1 = *(const float4*)(Ap + kt + 4);
        float4 wv0 = *(const float4*)(Wp + kt);
        float4 wv1 = *(const float4*)(Wp + kt + 4);
        {
            unsigned* d = &As[lr * 20 + lc];
            d[0] = f2tf(av0.x); d[1] = f2tf(av0.y); d[2] = f2tf(av0.z); d[3] = f2tf(av0.w);
            d[4] = f2tf(av1.x); d[5] = f2tf(av1.y); d[6] = f2tf(av1.z); d[7] = f2tf(av1.w);
            unsigned* e = &Bs[lr * 20 + lc];
            e[0] = f2tf(wv0.x); e[1] = f2tf(wv0.y); e[2] = f2tf(wv0.z); e[3] = f2tf(wv0.w);
            e[4] = f2tf(wv1.x); e[5] = f2tf(wv1.y); e[6] = f2tf(wv1.z); e[7] = f2tf(wv1.w);
        }
        __syncthreads();
#pragma unroll
        for (int ks = 0; ks < 2; ks++) {
            int k0 = ks * 8;
            unsigned af[2][4];
#pragma unroll
            for (int mt = 0; mt < 2; mt++) {
                int r = wm * 32 + mt * 16 + g;
                af[mt][0] = As[r * 20 + k0 + t];
                af[mt][1] = As[(r + 8) * 20 + k0 + t];
                af[mt][2] = As[r * 20 + k0 + t + 4];
                af[mt][3] = As[(r + 8) * 20 + k0 + t + 4];
            }
#pragma unroll
            for (int nt = 0; nt < 8; nt++) {
                int c = wn * 64 + nt * 8 + g;
                unsigned b0 = Bs[c * 20 + k0 + t];
                unsigned b1 = Bs[c * 20 + k0 + t + 4];
#pragma unroll
                for (int mt = 0; mt < 2; mt++)
                    mma_tf32(acc[mt][nt][0], acc[mt][nt][1], acc[mt][nt][2], acc[mt][nt][3],
                             af[mt][0], af[mt][1], af[mt][2], af[mt][3], b0, b1);
            }
        }
        __syncthreads();
    }

    // epilogue: rows r0 = bm + wm*32 + mt*16 + g (+8), cols n = bn + wn*64 + nt*8 + 2t (+1)
#pragma unroll
    for (int mt = 0; mt < 2; mt++) {
        int r0 = bm + wm * 32 + mt * 16 + g;
        int r1 = r0 + 8;
#pragma unroll
        for (int nt = 0; nt < 8; nt++) {
            int n = bn + wn * 64 + nt * 8 + t * 2;
            float v00 = acc[mt][nt][0] + bias[n];
            float v01 = acc[mt][nt][1] + bias[n + 1];
            float v10 = acc[mt][nt][2] + bias[n];
            float v11 = acc[mt][nt][3] + bias[n + 1];
            if (MODE == 0) {
                int sec = n >> 10;            // 0=q 1=k 2=v
                int c = n & 1023;
                int h = c >> 6, dd = c & 63;  // n,n+1 stay within the same head
                float* dst = (sec == 0) ? g_q : (sec == 1) ? g_k : g_v;
                {
                    int b = r0 >> 11, l = r0 & 2047;
                    float2 v = {v00, v01};
                    *(float2*)&dst[(((size_t)b * NH + h) * LS + l) * HD + dd] = v;
                }
                {
                    int b = r1 >> 11, l = r1 & 2047;
                    float2 v = {v10, v11};
                    *(float2*)&dst[(((size_t)b * NH + h) * LS + l) * HD + dd] = v;
                }
            } else {
                float2 va = {v00, v01};
                float2 vb = {v10, v11};
                *(float2*)&C[(size_t)r0 * N + n] = va;
                *(float2*)&C[(size_t)r1 * N + n] = vb;
            }
        }
    }
}

// ---------------- flash attention, tf32 tensor cores, static smem ----------------
// grid: (L/64, H, B), 128 threads (4 warps). Warp w owns q-rows [w*16, w*16+16).
// Q fragment lives entirely in registers (loaded once). Per k-tile (64 keys):
// S = Q@K^T via mma, warp-local online softmax, P overwrites the K smem buffer
// (all warps done reading K at that point), O += P@V via mma.
// K/P stride 68 (==4 mod 32), V stride 72 (==8 mod 32) -> conflict-free frag reads.
// Static smem: (64*68 + 64*72)*4 = 35840 B.
__global__ void __launch_bounds__(128, 3)
attn_tc(const float* __restrict__ bias_g) {
    __shared__ unsigned KPs[64 * 68];   // K tile, then P tile (aliased)
    __shared__ unsigned Vs[64 * 72];

    int b = blockIdx.z, h = blockIdx.y;
    int q0 = blockIdx.x * 64;
    int tid = threadIdx.x, lane = tid & 31, wid = tid >> 5;
    int g = lane >> 2, t = lane & 3;
    int wr = wid * 16;

    const float* Qg = g_q + (((size_t)b * NH + h) * LS + q0) * HD;
    const float* Kg = g_k + ((size_t)b * NH + h) * LS * HD;
    const float* Vg = g_v + ((size_t)b * NH + h) * LS * HD;
    const float* Bg = bias_g + (((size_t)b * NH + h) * LS + q0) * LS;

    // ---- load Q fragment into registers (one time) ----
    unsigned qa[8][4];
#pragma unroll
    for (int ks = 0; ks < 8; ks++) {
        int k0 = ks * 8;
        qa[ks][0] = f2tf(Qg[(size_t)(wr + g) * HD + k0 + t]);
        qa[ks][1] = f2tf(Qg[(size_t)(wr + g + 8) * HD + k0 + t]);
        qa[ks][2] = f2tf(Qg[(size_t)(wr + g) * HD + k0 + t + 4]);
        qa[ks][3] = f2tf(Qg[(size_t)(wr + g + 8) * HD + k0 + t + 4]);
    }

    float m0 = -INFINITY, m1 = -INFINITY, l0 = 0.f, l1 = 0.f;
    float o[8][4];
#pragma unroll
    for (int nt = 0; nt < 8; nt++)
#pragma unroll
        for (int i = 0; i < 4; i++) o[nt][i] = 0.f;

    for (int kt = 0; kt < LS; kt += 64) {
        __syncthreads();   // prev tile's P/V consumers done
        {
            int r = tid >> 1, c0 = (tid & 1) * 32;
#pragma unroll
            for (int j = 0; j < 8; j++) {
                int c = c0 + j * 4;
                float4 kv = *(const float4*)(Kg + (size_t)(kt + r) * HD + c);
                unsigned* kd = &KPs[r * 68 + c];
                kd[0] = f2tf(kv.x); kd[1] = f2tf(kv.y); kd[2] = f2tf(kv.z); kd[3] = f2tf(kv.w);
                float4 vv = *(const float4*)(Vg + (size_t)(kt + r) * HD + c);
                unsigned* vd = &Vs[r * 72 + c];
                vd[0] = f2tf(vv.x); vd[1] = f2tf(vv.y); vd[2] = f2tf(vv.z); vd[3] = f2tf(vv.w);
            }
        }
        __syncthreads();

        // ---- S = Q @ K^T ----
        float s[8][4];
#pragma unroll
        for (int nt = 0; nt < 8; nt++)
#pragma unroll
            for (int i = 0; i < 4; i++) s[nt][i] = 0.f;

#pragma unroll
        for (int ks = 0; ks < 8; ks++) {
            int k0 = ks * 8;
#pragma unroll
            for (int nt = 0; nt < 8; nt++) {
                int key = nt * 8 + g;
                unsigned b0 = KPs[key * 68 + k0 + t];
                unsigned b1 = KPs[key * 68 + k0 + t + 4];
                mma_tf32(s[nt][0], s[nt][1], s[nt][2], s[nt][3],
                         qa[ks][0], qa[ks][1], qa[ks][2], qa[ks][3], b0, b1);
            }
        }

        // ---- scale + bias + key-padding penalty; row max ----
        float rmax0 = -INFINITY, rmax1 = -INFINITY;
#pragma unroll
        for (int nt = 0; nt < 8; nt++) {
            int col = kt + nt * 8 + t * 2;
            float2 bz0 = *(const float2*)(Bg + (size_t)(wr + g) * LS + col);
            float2 bz1 = *(const float2*)(Bg + (size_t)(wr + g + 8) * LS + col);
            float2 pen = *(const float2*)(g_maskpen + b * LS + col);
            s[nt][0] = s[nt][0] * 0.125f + bz0.x - pen.x;
            s[nt][1] = s[nt][1] * 0.125f + bz0.y - pen.y;
            s[nt][2] = s[nt][2] * 0.125f + bz1.x - pen.x;
            s[nt][3] = s[nt][3] * 0.125f + bz1.y - pen.y;
            rmax0 = fmaxf(rmax0, fmaxf(s[nt][0], s[nt][1]));
            rmax1 = fmaxf(rmax1, fmaxf(s[nt][2], s[nt][3]));
        }
        rmax0 = fmaxf(rmax0, __shfl_xor_sync(0xffffffffu, rmax0, 1));
        rmax0 = fmaxf(rmax0, __shfl_xor_sync(0xffffffffu, rmax0, 2));
        rmax1 = fmaxf(rmax1, __shfl_xor_sync(0xffffffffu, rmax1, 1));
        rmax1 = fmaxf(rmax1, __shfl_xor_sync(0xffffffffu, rmax1, 2));

        float mn0 = fmaxf(m0, rmax0), mn1 = fmaxf(m1, rmax1);
        float sc0 = __expf(m0 - mn0), sc1 = __expf(m1 - mn1);
        m0 = mn0; m1 = mn1;

        __syncthreads();   // ALL warps done reading KPs as K -> safe to overwrite with P

        float rs0 = 0.f, rs1 = 0.f;
#pragma unroll
        for (int nt = 0; nt < 8; nt++) {
            float p0 = __expf(fmaxf(s[nt][0] - mn0, -CLAMP_F));
            float p1 = __expf(fmaxf(s[nt][1] - mn0, -CLAMP_F));
            float p2 = __expf(fmaxf(s[nt][2] - mn1, -CLAMP_F));
            float p3 = __expf(fmaxf(s[nt][3] - mn1, -CLAMP_F));
            rs0 += p0 + p1;
            rs1 += p2 + p3;
            unsigned* pd0 = &KPs[(wr + g) * 68 + nt * 8 + t * 2];
            pd0[0] = f2tf(p0); pd0[1] = f2tf(p1);
            unsigned* pd1 = &KPs[(wr + g + 8) * 68 + nt * 8 + t * 2];
            pd1[0] = f2tf(p2); pd1[1] = f2tf(p3);
        }
        rs0 += __shfl_xor_sync(0xffffffffu, rs0, 1);
        rs0 += __shfl_xor_sync(0xffffffffu, rs0, 2);
        rs1 += __shfl_xor_sync(0xffffffffu, rs1, 1);
        rs1 += __shfl_xor_sync(0xffffffffu, rs1, 2);
        l0 = l0 * sc0 + rs0;
        l1 = l1 * sc1 + rs1;
#pragma unroll
        for (int nt = 0; nt < 8; nt++) {
            o[nt][0] *= sc0; o[nt][1] *= sc0;
            o[nt][2] *= sc1; o[nt][3] *= sc1;
        }
        __syncwarp();   // own warp's P rows visible (only own rows are read below)

        // ---- O += P @ V ----
#pragma unroll
        for (int ks = 0; ks < 8; ks++) {
            int k0 = ks * 8;
            unsigned a0 = KPs[(wr + g) * 68 + k0 + t];
            unsigned a1 = KPs[(wr + g + 8) * 68 + k0 + t];
            unsigned a2 = KPs[(wr + g) * 68 + k0 + t + 4];
            unsigned a3 = KPs[(wr + g + 8) * 68 + k0 + t + 4];
#pragma unroll
            for (int nt = 0; nt < 8; nt++) {
                unsigned b0 = Vs[(k0 + t) * 72 + nt * 8 + g];
                unsigned b1 = Vs[(k0 + t + 4) * 72 + nt * 8 + g];
                mma_tf32(o[nt][0], o[nt][1], o[nt][2], o[nt][3], a0, a1, a2, a3, b0, b1);
            }
        }
    }

    // normalize + write [B,L,D]
    float inv0 = 1.0f / l0, inv1 = 1.0f / l1;
    size_t base0 = ((size_t)b * LS + q0 + wr + g) * DM + h * HD;
    size_t base1 = ((size_t)b * LS + q0 + wr + g + 8) * DM + h * HD;
#pragma unroll
    for (int nt = 0; nt < 8; nt++) {
        int c = nt * 8 + t * 2;
        float2 v0 = {o[nt][0] * inv0, o[nt][1] * inv0};
        float2 v1 = {o[nt][2] * inv1, o[nt][3] * inv1};
        *(float2*)(g_attn + base0 + c) = v0;
        *(float2*)(g_attn + base1 + c) = v1;
    }
}

extern "C" void kernel_launch(void* const* d_in, const int* in_sizes, int n_in,
                              void* d_out, int out_size) {
    const float* x          = (const float*)d_in[0];
    const unsigned char* km = (const unsigned char*)d_in[1];
    const float* attn_bias  = (const float*)d_in[2];
    const float* W_in       = (const float*)d_in[3];
    const float* b_in       = (const float*)d_in[4];
    const float* W_out      = (const float*)d_in[5];
    const float* b_out      = (const float*)d_in[6];
    float* out              = (float*)d_out;
    (void)in_sizes; (void)n_in; (void)out_size;

    mask_kernel<<<1, 256>>>(km);

    // QKV: [4096,1024] @ [3072,1024]^T
    {
        dim3 grid(3072 / 128, 4096 / 128);
        gemm_tc<0><<<grid, 256>>>(x, W_in, b_in, nullptr, NB * LS, 3 * DM, DM);
    }
    // attention
    {
        dim3 grid(LS / 64, NH, NB);
        attn_tc<<<grid, 128>>>(attn_bias);
    }
    // out-proj: [4096,1024] @ [1024,1024]^T
    {
        dim3 grid(1024 / 128, 4096 / 128);
        gemm_tc<1><<<grid, 256>>>(nullptr, W_out, b_out, out, NB * LS, DM, DM);
    }
}